// round 4
// baseline (speedup 1.0000x reference)
#include <cuda_runtime.h>

#define T_LEN 5000
#define HID   64
#define BATCH 256

typedef unsigned long long u64t;

// ---- packed f32x2 helpers (FFMA2/ADD2 only reachable via PTX) ----
__device__ __forceinline__ u64t pack2(float lo, float hi) {
    u64t d;
    asm("mov.b64 %0, {%1, %2};" : "=l"(d) : "f"(lo), "f"(hi));
    return d;
}
__device__ __forceinline__ void unpack2(u64t v, float& lo, float& hi) {
    asm("mov.b64 {%0, %1}, %2;" : "=f"(lo), "=f"(hi) : "l"(v));
}
__device__ __forceinline__ u64t ffma2(u64t a, u64t b, u64t c) {
    u64t d;
    asm("fma.rn.f32x2 %0, %1, %2, %3;" : "=l"(d) : "l"(a), "l"(b), "l"(c));
    return d;
}
__device__ __forceinline__ u64t add2(u64t a, u64t b) {
    u64t d;
    asm("add.rn.f32x2 %0, %1, %2;" : "=l"(d) : "l"(a), "l"(b));
    return d;
}

__device__ __forceinline__ float sigmoidf_(float x) {
    return __fdividef(1.0f, 1.0f + __expf(-x));
}
// tanh via 1 - 2/(e^{2x}+1): overflow-safe at both ends
__device__ __forceinline__ float tanhf_(float x) {
    float e = __expf(2.0f * x);
    return 1.0f - __fdividef(2.0f, e + 1.0f);
}

__global__ __launch_bounds__(256, 2)
void lstm_fused_kernel(const float* __restrict__ x,
                       const float* __restrict__ W_ih,
                       const float* __restrict__ W_hh,
                       const float* __restrict__ b_ih,
                       const float* __restrict__ b_hh,
                       const float* __restrict__ W_fc,
                       const float* __restrict__ b_fc,
                       float* __restrict__ out)
{
    __shared__ __align__(16) float x_sh[T_LEN];   // whole input row (20 KB)
    __shared__ float acts_sh[4 * HID];            // activated gates, [g*64+u]
    __shared__ __align__(16) float h_sh[HID];     // hidden state (contiguous)

    const int tid = threadIdx.x;
    const int row = blockIdx.x;

    // ---- stage the full x row into SMEM, coalesced float4 ----
    {
        const float4* xr = reinterpret_cast<const float4*>(x + row * T_LEN);
        float4* xs = reinterpret_cast<float4*>(x_sh);
        for (int i = tid; i < T_LEN / 4; i += 256) xs[i] = xr[i];
    }

    // ---- one gate-row per thread: tid = g*64 + u ----
    const int g   = tid >> 6;       // 0:i 1:f 2:g 3:o
    const int u   = tid & 63;       // hidden unit
    const int grow = g * HID + u;   // row in W_hh / index in biases

    // ---- W_hh row packed horizontally: w2[j] = (W[grow,2j], W[grow,2j+1]) ----
    u64t w2[HID / 2];               // 32 x b64 = 64 regs
    {
        const float4* r = reinterpret_cast<const float4*>(W_hh + grow * HID);
        #pragma unroll
        for (int i = 0; i < HID / 4; i++) {
            float4 v = r[i];
            w2[2 * i + 0] = pack2(v.x, v.y);
            w2[2 * i + 1] = pack2(v.z, v.w);
        }
    }
    const float wih  = W_ih[grow];
    const float base = b_ih[grow] + b_hh[grow];

    if (tid < HID) h_sh[tid] = 0.0f;
    float c = 0.0f;                 // live only in threads 0..63 (g==0)
    __syncthreads();                // covers x_sh staging + h init

    // ================= recurrence: 5000 serial steps =================
    for (int t = 0; t < T_LEN; t++) {
        // scalar part overlaps with the LDS-fed chain below
        const float xpart = fmaf(x_sh[t], wih, base);

        // 4 independent accumulator chains, 8 deps each
        u64t a0 = 0ULL, a1 = 0ULL, a2 = 0ULL, a3 = 0ULL;
        const ulonglong2* hp = reinterpret_cast<const ulonglong2*>(h_sh);
        #pragma unroll
        for (int j = 0; j < HID / 8; j++) {        // 8 iters, 4 pairs each
            ulonglong2 hv0 = hp[2 * j];
            ulonglong2 hv1 = hp[2 * j + 1];
            a0 = ffma2(hv0.x, w2[4 * j + 0], a0);
            a1 = ffma2(hv0.y, w2[4 * j + 1], a1);
            a2 = ffma2(hv1.x, w2[4 * j + 2], a2);
            a3 = ffma2(hv1.y, w2[4 * j + 3], a3);
        }
        u64t s = add2(add2(a0, a1), add2(a2, a3));
        float lo, hi;
        unpack2(s, lo, hi);
        const float pre = xpart + lo + hi;

        // activation by gate role (MUFU work spread over all 8 warps)
        const float act = (g == 2) ? tanhf_(pre) : sigmoidf_(pre);
        acts_sh[grow] = act;
        __syncthreads();

        // c/h update on warps 0-1 only; other warps go straight to the barrier
        if (tid < HID) {
            float iv = acts_sh[tid];
            float fv = acts_sh[HID + tid];
            float gv = acts_sh[2 * HID + tid];
            float ov = acts_sh[3 * HID + tid];
            c = fmaf(fv, c, iv * gv);
            h_sh[tid] = ov * tanhf_(c);
        }
        __syncthreads();
    }

    // ================= FC(64 -> 128) + ReLU epilogue =================
    if (tid < 128) {
        const float4* wr = reinterpret_cast<const float4*>(W_fc + tid * HID);
        float acc = b_fc[tid];
        #pragma unroll
        for (int i = 0; i < HID / 4; i++) {
            float4 w = wr[i];
            acc += h_sh[4 * i + 0] * w.x;
            acc += h_sh[4 * i + 1] * w.y;
            acc += h_sh[4 * i + 2] * w.z;
            acc += h_sh[4 * i + 3] * w.w;
        }
        out[row * 128 + tid] = fmaxf(acc, 0.0f);
    }
}

extern "C" void kernel_launch(void* const* d_in, const int* in_sizes, int n_in,
                              void* d_out, int out_size)
{
    const float* x    = (const float*)d_in[0];
    const float* W_ih = (const float*)d_in[1];
    const float* W_hh = (const float*)d_in[2];
    const float* b_ih = (const float*)d_in[3];
    const float* b_hh = (const float*)d_in[4];
    const float* W_fc = (const float*)d_in[5];
    const float* b_fc = (const float*)d_in[6];

    lstm_fused_kernel<<<BATCH, 256>>>(x, W_ih, W_hh, b_ih, b_hh,
                                      W_fc, b_fc, (float*)d_out);
}

// round 9
// speedup vs baseline: 1.3077x; 1.3077x over previous
#include <cuda_runtime.h>

#define T_LEN 5000
#define HID   64
#define BATCH 256

typedef unsigned long long u64t;

// ---- packed f32x2 helpers ----
__device__ __forceinline__ u64t pack2(float lo, float hi) {
    u64t d;
    asm("mov.b64 %0, {%1, %2};" : "=l"(d) : "f"(lo), "f"(hi));
    return d;
}
__device__ __forceinline__ void unpack2(u64t v, float& lo, float& hi) {
    asm("mov.b64 {%0, %1}, %2;" : "=f"(lo), "=f"(hi) : "l"(v));
}
__device__ __forceinline__ u64t ffma2(u64t a, u64t b, u64t c) {
    u64t d;
    asm("fma.rn.f32x2 %0, %1, %2, %3;" : "=l"(d) : "l"(a), "l"(b), "l"(c));
    return d;
}
__device__ __forceinline__ u64t add2(u64t a, u64t b) {
    u64t d;
    asm("add.rn.f32x2 %0, %1, %2;" : "=l"(d) : "l"(a), "l"(b));
    return d;
}
__device__ __forceinline__ u64t shfl_bfly1_u64(u64t v) {
    float lo, hi;
    unpack2(v, lo, hi);
    lo = __shfl_xor_sync(0xffffffffu, lo, 1);
    hi = __shfl_xor_sync(0xffffffffu, hi, 1);
    return pack2(lo, hi);
}

__device__ __forceinline__ float sigmoidf_(float x) {
    return __fdividef(1.0f, 1.0f + __expf(-x));
}
// tanh via 1 - 2/(e^{2x}+1): overflow-safe at both ends
__device__ __forceinline__ float tanhf_(float x) {
    float e = __expf(2.0f * x);
    return 1.0f - __fdividef(2.0f, e + 1.0f);
}

__global__ __launch_bounds__(128, 2)
void lstm_fused_kernel(const float* __restrict__ x,
                       const float* __restrict__ W_ih,
                       const float* __restrict__ W_hh,
                       const float* __restrict__ b_ih,
                       const float* __restrict__ b_hh,
                       const float* __restrict__ W_fc,
                       const float* __restrict__ b_fc,
                       float* __restrict__ out)
{
    __shared__ __align__(16) float x_sh[T_LEN];   // whole input row (20 KB)
    __shared__ __align__(16) float h_sh[HID];     // hidden state

    const int tid = threadIdx.x;
    const int row = blockIdx.x;

    // ---- stage the full x row into SMEM, coalesced float4 ----
    {
        const float4* xr = reinterpret_cast<const float4*>(x + row * T_LEN);
        float4* xs = reinterpret_cast<float4*>(x_sh);
        for (int i = tid; i < T_LEN / 4; i += 128) xs[i] = xr[i];
    }

    // ---- thread = (unit u, k-half): all 4 gates of u, 32 of 64 k each ----
    const int u    = tid >> 1;
    const int half = tid & 1;        // partner = lane^1, same warp
    const int kofs = half * 32;

    // ---- weights: 4 gate rows x 16 k-pairs -> 64 u64 regs ----
    u64t w2[64];
    #pragma unroll
    for (int gi = 0; gi < 4; gi++) {
        const float4* wr =
            reinterpret_cast<const float4*>(W_hh + (gi * HID + u) * HID + kofs);
        #pragma unroll
        for (int j = 0; j < 8; j++) {
            float4 v = wr[j];
            w2[gi * 16 + 2 * j + 0] = pack2(v.x, v.y);
            w2[gi * 16 + 2 * j + 1] = pack2(v.z, v.w);
        }
    }

    // x-term + bias folded into chain init; only half==0 contributes them
    // (otherwise the bfly-sum would double-count).
    u64t wih2[4], b2[4];
    #pragma unroll
    for (int gi = 0; gi < 4; gi++) {
        const int r = gi * HID + u;
        wih2[gi] = half ? 0ULL : pack2(W_ih[r], 0.0f);
        b2[gi]   = half ? 0ULL : pack2(b_ih[r] + b_hh[r], 0.0f);
    }

    if (tid < HID) h_sh[tid] = 0.0f;
    float c = 0.0f;                  // redundant in both partner lanes
    __syncthreads();

    const ulonglong2* hp = reinterpret_cast<const ulonglong2*>(h_sh + kofs);

    // ================= recurrence: 5000 serial steps =================
    for (int t = 0; t < T_LEN; t++) {
        const float xv = x_sh[t];
        const u64t x2 = pack2(xv, xv);

        // 4 per-gate chains over this thread's k-half
        u64t ai_ = ffma2(x2, wih2[0], b2[0]);
        u64t af_ = ffma2(x2, wih2[1], b2[1]);
        u64t ag_ = ffma2(x2, wih2[2], b2[2]);
        u64t ao_ = ffma2(x2, wih2[3], b2[3]);

        #pragma unroll
        for (int j = 0; j < 8; j++) {
            ulonglong2 hv = hp[j];   // 4 h values = 2 packed pairs
            ai_ = ffma2(hv.x, w2[ 0 + 2 * j], ai_);
            ai_ = ffma2(hv.y, w2[ 1 + 2 * j], ai_);
            af_ = ffma2(hv.x, w2[16 + 2 * j], af_);
            af_ = ffma2(hv.y, w2[17 + 2 * j], af_);
            ag_ = ffma2(hv.x, w2[32 + 2 * j], ag_);
            ag_ = ffma2(hv.y, w2[33 + 2 * j], ag_);
            ao_ = ffma2(hv.x, w2[48 + 2 * j], ao_);
            ao_ = ffma2(hv.y, w2[49 + 2 * j], ao_);
        }

        // horizontal sums -> 4 partial preacts, packed as 2 u64
        float l, h2;
        unpack2(ai_, l, h2); const float pi_p = l + h2;
        unpack2(af_, l, h2); const float pf_p = l + h2;
        unpack2(ag_, l, h2); const float pg_p = l + h2;
        unpack2(ao_, l, h2); const float po_p = l + h2;

        u64t s_if = pack2(pi_p, pf_p);
        u64t s_go = pack2(pg_p, po_p);

        // cross-half reduction via butterfly shuffle (replaces STS+BAR+LDS)
        s_if = add2(s_if, shfl_bfly1_u64(s_if));
        s_go = add2(s_go, shfl_bfly1_u64(s_go));

        float pi, pf, pg, po;
        unpack2(s_if, pi, pf);
        unpack2(s_go, pg, po);

        // thread-local gate activations + state update (redundant per pair,
        // bit-exact: add2 is commutative)
        const float iv = sigmoidf_(pi);
        const float fv = sigmoidf_(pf);
        const float gv = tanhf_(pg);
        const float ov = sigmoidf_(po);
        c = fmaf(fv, c, iv * gv);
        const float hval = ov * tanhf_(c);

        if (!half) h_sh[u] = hval;   // one writer per unit
        __syncthreads();             // single barrier per step
    }

    // ================= FC(64 -> 128) + ReLU epilogue =================
    {
        const float4* wr = reinterpret_cast<const float4*>(W_fc + tid * HID);
        float acc = b_fc[tid];
        #pragma unroll
        for (int i = 0; i < HID / 4; i++) {
            float4 w = wr[i];
            acc += h_sh[4 * i + 0] * w.x;
            acc += h_sh[4 * i + 1] * w.y;
            acc += h_sh[4 * i + 2] * w.z;
            acc += h_sh[4 * i + 3] * w.w;
        }
        out[row * 128 + tid] = fmaxf(acc, 0.0f);
    }
}

extern "C" void kernel_launch(void* const* d_in, const int* in_sizes, int n_in,
                              void* d_out, int out_size)
{
    const float* x    = (const float*)d_in[0];
    const float* W_ih = (const float*)d_in[1];
    const float* W_hh = (const float*)d_in[2];
    const float* b_ih = (const float*)d_in[3];
    const float* b_hh = (const float*)d_in[4];
    const float* W_fc = (const float*)d_in[5];
    const float* b_fc = (const float*)d_in[6];

    lstm_fused_kernel<<<BATCH, 128>>>(x, W_ih, W_hh, b_ih, b_hh,
                                      W_fc, b_fc, (float*)d_out);
}

// round 11
// speedup vs baseline: 1.7097x; 1.3074x over previous
#include <cuda_runtime.h>

#define T_LEN 5000
#define HID   64
#define BATCH 256

typedef unsigned long long u64t;

// ---- packed f32x2 helpers ----
__device__ __forceinline__ u64t pack2(float lo, float hi) {
    u64t d;
    asm("mov.b64 %0, {%1, %2};" : "=l"(d) : "f"(lo), "f"(hi));
    return d;
}
__device__ __forceinline__ void unpack2(u64t v, float& lo, float& hi) {
    asm("mov.b64 {%0, %1}, %2;" : "=f"(lo), "=f"(hi) : "l"(v));
}
__device__ __forceinline__ u64t ffma2(u64t a, u64t b, u64t c) {
    u64t d;
    asm("fma.rn.f32x2 %0, %1, %2, %3;" : "=l"(d) : "l"(a), "l"(b), "l"(c));
    return d;
}
__device__ __forceinline__ u64t add2(u64t a, u64t b) {
    u64t d;
    asm("add.rn.f32x2 %0, %1, %2;" : "=l"(d) : "l"(a), "l"(b));
    return d;
}
__device__ __forceinline__ u64t shfl_bfly1_u64(u64t v) {
    float lo, hi;
    unpack2(v, lo, hi);
    lo = __shfl_xor_sync(0xffffffffu, lo, 1);
    hi = __shfl_xor_sync(0xffffffffu, hi, 1);
    return pack2(lo, hi);
}

// ---- hardware tanh (sm_75+): single MUFU op, lat ~16 ----
__device__ __forceinline__ float tanh_hw(float x) {
    float r;
    asm("tanh.approx.f32 %0, %1;" : "=f"(r) : "f"(x));
    return r;
}
// sigmoid(x) = 0.5*tanh(0.5x) + 0.5  (mul + tanh + fma ~ 24 cy)
__device__ __forceinline__ float sigmoid_hw(float x) {
    return fmaf(0.5f, tanh_hw(0.5f * x), 0.5f);
}

__global__ __launch_bounds__(128, 2)
void lstm_fused_kernel(const float* __restrict__ x,
                       const float* __restrict__ W_ih,
                       const float* __restrict__ W_hh,
                       const float* __restrict__ b_ih,
                       const float* __restrict__ b_hh,
                       const float* __restrict__ W_fc,
                       const float* __restrict__ b_fc,
                       float* __restrict__ out)
{
    __shared__ __align__(16) float x_sh[T_LEN];   // whole input row (20 KB)
    __shared__ __align__(16) float h_sh[HID];     // hidden state

    const int tid = threadIdx.x;
    const int row = blockIdx.x;

    // ---- stage the full x row into SMEM, coalesced float4 ----
    {
        const float4* xr = reinterpret_cast<const float4*>(x + row * T_LEN);
        float4* xs = reinterpret_cast<float4*>(x_sh);
        for (int i = tid; i < T_LEN / 4; i += 128) xs[i] = xr[i];
    }

    // ---- thread = (unit u, k-half): all 4 gates of u, 32 of 64 k each ----
    const int u    = tid >> 1;
    const int half = tid & 1;        // partner = lane^1, same warp
    const int kofs = half * 32;

    // ---- weights: 4 gate rows x 16 k-pairs -> 64 u64 regs ----
    u64t w2[64];
    #pragma unroll
    for (int gi = 0; gi < 4; gi++) {
        const float4* wr =
            reinterpret_cast<const float4*>(W_hh + (gi * HID + u) * HID + kofs);
        #pragma unroll
        for (int j = 0; j < 8; j++) {
            float4 v = wr[j];
            w2[gi * 16 + 2 * j + 0] = pack2(v.x, v.y);
            w2[gi * 16 + 2 * j + 1] = pack2(v.z, v.w);
        }
    }

    // x-term + bias folded into chain init; only half==0 contributes them
    // (otherwise the bfly-sum would double-count).
    u64t wih2[4], b2[4];
    #pragma unroll
    for (int gi = 0; gi < 4; gi++) {
        const int r = gi * HID + u;
        wih2[gi] = half ? 0ULL : pack2(W_ih[r], 0.0f);
        b2[gi]   = half ? 0ULL : pack2(b_ih[r] + b_hh[r], 0.0f);
    }

    if (tid < HID) h_sh[tid] = 0.0f;
    float c = 0.0f;                  // redundant in both partner lanes
    __syncthreads();

    // ---- phase-skew: odd blocks delay ~256 cy so co-resident CTAs
    //      interleave FMA phase with tail phase instead of phase-locking ----
    if (blockIdx.x & 1) {
        float d = 1.0f;
        #pragma unroll
        for (int i = 0; i < 64; i++) {
            d = fmaf(d, 1.0000001f, 1e-20f);
            asm volatile("" : "+f"(d));   // keep the dependent chain alive
        }
    }

    const ulonglong2* hp = reinterpret_cast<const ulonglong2*>(h_sh + kofs);

    // ================= recurrence: 5000 serial steps =================
    for (int t = 0; t < T_LEN; t++) {
        const float xv = x_sh[t];
        const u64t x2 = pack2(xv, xv);

        // 4 per-gate chains over this thread's k-half
        u64t ai_ = ffma2(x2, wih2[0], b2[0]);
        u64t af_ = ffma2(x2, wih2[1], b2[1]);
        u64t ag_ = ffma2(x2, wih2[2], b2[2]);
        u64t ao_ = ffma2(x2, wih2[3], b2[3]);

        #pragma unroll
        for (int j = 0; j < 8; j++) {
            ulonglong2 hv = hp[j];   // 4 h values = 2 packed pairs
            ai_ = ffma2(hv.x, w2[ 0 + 2 * j], ai_);
            ai_ = ffma2(hv.y, w2[ 1 + 2 * j], ai_);
            af_ = ffma2(hv.x, w2[16 + 2 * j], af_);
            af_ = ffma2(hv.y, w2[17 + 2 * j], af_);
            ag_ = ffma2(hv.x, w2[32 + 2 * j], ag_);
            ag_ = ffma2(hv.y, w2[33 + 2 * j], ag_);
            ao_ = ffma2(hv.x, w2[48 + 2 * j], ao_);
            ao_ = ffma2(hv.y, w2[49 + 2 * j], ao_);
        }

        // horizontal sums -> 4 partial preacts, packed as 2 u64
        float l, h2;
        unpack2(ai_, l, h2); const float pi_p = l + h2;
        unpack2(af_, l, h2); const float pf_p = l + h2;
        unpack2(ag_, l, h2); const float pg_p = l + h2;
        unpack2(ao_, l, h2); const float po_p = l + h2;

        u64t s_if = pack2(pi_p, pf_p);
        u64t s_go = pack2(pg_p, po_p);

        // cross-half reduction via butterfly shuffle (replaces STS+BAR+LDS)
        s_if = add2(s_if, shfl_bfly1_u64(s_if));
        s_go = add2(s_go, shfl_bfly1_u64(s_go));

        float pi, pf, pg, po;
        unpack2(s_if, pi, pf);
        unpack2(s_go, pg, po);

        // HW-tanh activations + state update (redundant per lane pair,
        // bit-exact across the pair: add2 is commutative)
        const float iv = sigmoid_hw(pi);
        const float fv = sigmoid_hw(pf);
        const float gv = tanh_hw(pg);
        const float ov = sigmoid_hw(po);
        c = fmaf(fv, c, iv * gv);
        const float hval = ov * tanh_hw(c);

        if (!half) h_sh[u] = hval;   // one writer per unit
        __syncthreads();             // single barrier per step
    }

    // ================= FC(64 -> 128) + ReLU epilogue =================
    {
        const float4* wr = reinterpret_cast<const float4*>(W_fc + tid * HID);
        float acc = b_fc[tid];
        #pragma unroll
        for (int i = 0; i < HID / 4; i++) {
            float4 w = wr[i];
            acc += h_sh[4 * i + 0] * w.x;
            acc += h_sh[4 * i + 1] * w.y;
            acc += h_sh[4 * i + 2] * w.z;
            acc += h_sh[4 * i + 3] * w.w;
        }
        out[row * 128 + tid] = fmaxf(acc, 0.0f);
    }
}

extern "C" void kernel_launch(void* const* d_in, const int* in_sizes, int n_in,
                              void* d_out, int out_size)
{
    const float* x    = (const float*)d_in[0];
    const float* W_ih = (const float*)d_in[1];
    const float* W_hh = (const float*)d_in[2];
    const float* b_ih = (const float*)d_in[3];
    const float* b_hh = (const float*)d_in[4];
    const float* W_fc = (const float*)d_in[5];
    const float* b_fc = (const float*)d_in[6];

    lstm_fused_kernel<<<BATCH, 128>>>(x, W_ih, W_hh, b_ih, b_hh,
                                      W_fc, b_fc, (float*)d_out);
}